// round 7
// baseline (speedup 1.0000x reference)
#include <cuda_runtime.h>
#include <math.h>

// NeRF-style renderer: B=1, H=W=200, FOCAL=300, NEAR=2, FAR=6, S=128, F=8.
// SEG=4 threads/pixel, 32 samples each, exact width-4 warp-shuffle combine.
// Inner math packed along feature pairs with fma.rn.f32x2 (FFMA2):
//   relu via f2 = x + |x| (=2*relu), with 0.5 folded into density/color weights;
//   dn folded into density weights; exp/sigmoid via raw ex2/rcp with log2(e)
//   folded into staged constants.
// Output: color_map [200*200*3] then depth_map [200*200] (fp32).

#define H 200
#define W 200
#define NPIX (H * W)
#define S 128
#define F 8
#define SEG 4
#define SPT (S / SEG)          // 32
#define FOCAL 300.0f
#define NEARP 2.0f
#define FARP 6.0f
#define L2E 1.4426950408889634f

typedef unsigned long long u64;

__device__ __forceinline__ float ex2f(float x) {
    float r; asm("ex2.approx.f32 %0, %1;" : "=f"(r) : "f"(x)); return r;
}
__device__ __forceinline__ float rcpf(float x) {
    float r; asm("rcp.approx.f32 %0, %1;" : "=f"(r) : "f"(x)); return r;
}
__device__ __forceinline__ u64 pack2(float lo, float hi) {
    u64 r; asm("mov.b64 %0, {%1, %2};" : "=l"(r) : "f"(lo), "f"(hi)); return r;
}
__device__ __forceinline__ void unpack2(u64 v, float& lo, float& hi) {
    asm("mov.b64 {%0, %1}, %2;" : "=f"(lo), "=f"(hi) : "l"(v));
}
#define FMA2(d, a, b, c) asm("fma.rn.f32x2 %0, %1, %2, %3;" : "=l"(d) : "l"(a), "l"(b), "l"(c))
#define ADD2(d, a, b)    asm("add.rn.f32x2 %0, %1, %2;"     : "=l"(d) : "l"(a), "l"(b))
#define ABS2(d, a)       asm("and.b64 %0, %1, 0x7FFFFFFF7FFFFFFF;" : "=l"(d) : "l"(a))

__global__ __launch_bounds__(128, 8)
void render_kernel(const float* __restrict__ positions,
                   const float* __restrict__ forwards,
                   const float* __restrict__ ups,
                   const float* __restrict__ normal,
                   const float* __restrict__ Wf,
                   const float* __restrict__ bf,
                   const float* __restrict__ Wd,
                   const float* __restrict__ bd,
                   const float* __restrict__ Wc,
                   const float* __restrict__ bc,
                   float* __restrict__ out)
{
    // ---- shared staging ----
    // sample s = q*SPT + i lives at slot i*SEG + q.
    __shared__ float2 s_tt[S];        // (t, t) duplicated for packed broadcast
    __shared__ float  s_dl[S];        // -delta_raw * log2(e)
    __shared__ float  s_Wf[3][F];
    __shared__ float  s_WdFh[F];      // 0.5 * Wd_feat
    __shared__ float  s_WcFh[F][3];   // -0.5*log2(e) * Wc_feat
    __shared__ float  s_cam[12];      // right(3), up(3), fwd(3), pos(3)
    __shared__ float  s_Wd3[3];
    __shared__ float  s_negWc3[3][3]; // -log2(e) * Wc_dir
    __shared__ float  s_negbc[3];     // -log2(e) * bc
    __shared__ float  s_bf[F];
    __shared__ float  s_bd;

    const int tid = threadIdx.x;

    if (tid < S) {
        float n0 = normal[tid];
        int xi = (tid % SPT) * SEG + (tid / SPT);
        float t = NEARP + n0 * (FARP - NEARP);
        float dl = (tid < S - 1) ? (normal[tid + 1] - n0) * (FARP - NEARP)
                                 : 1e10f;
        s_tt[xi] = make_float2(t, t);
        s_dl[xi] = -dl * L2E;
    }
    if (tid < 24) s_Wf[tid / F][tid % F] = Wf[tid];
    if (tid >= 32 && tid < 32 + F) {
        int j = tid - 32;
        s_WdFh[j] = 0.5f * Wd[3 + j];
        s_bf[j] = bf[j];
    }
    if (tid >= 40 && tid < 40 + 24) {
        int k = tid - 40;
        s_WcFh[k / 3][k % 3] = -0.5f * L2E * Wc[(3 + k / 3) * 3 + (k % 3)];
    }
    if (tid == 0) {
        float ux = ups[0], uy = ups[1], uz = ups[2];
        float fx = forwards[0], fy = forwards[1], fz = forwards[2];
        s_cam[0] = uy * fz - uz * fy;
        s_cam[1] = uz * fx - ux * fz;
        s_cam[2] = ux * fy - uy * fx;
        s_cam[3] = ux; s_cam[4] = uy; s_cam[5] = uz;
        s_cam[6] = fx; s_cam[7] = fy; s_cam[8] = fz;
        s_cam[9] = positions[0]; s_cam[10] = positions[1]; s_cam[11] = positions[2];
        s_Wd3[0] = Wd[0]; s_Wd3[1] = Wd[1]; s_Wd3[2] = Wd[2];
        s_bd = bd[0];
        #pragma unroll
        for (int j = 0; j < 3; j++) {
            s_negbc[j] = -L2E * bc[j];
            #pragma unroll
            for (int i = 0; i < 3; i++) s_negWc3[j][i] = -L2E * Wc[j * 3 + i];
        }
    }
    __syncthreads();

    const int gtid = blockIdx.x * blockDim.x + tid;   // 160,000 threads
    const int pix = gtid >> 2;
    const int q = gtid & 3;

    const int h = pix / W;
    const int w = pix - h * W;

    const float a = ((float)h - (H * 0.5f - 0.5f)) * (1.0f / FOCAL);
    const float b = -((float)w - (W * 0.5f - 0.5f)) * (1.0f / FOCAL);

    const float dx = a * s_cam[0] + b * s_cam[3] + s_cam[6];
    const float dy = a * s_cam[1] + b * s_cam[4] + s_cam[7];
    const float dz = a * s_cam[2] + b * s_cam[5] + s_cam[8];
    const float dn = sqrtf(dx * dx + dy * dy + dz * dz);

    const float px = s_cam[9], py = s_cam[10], pz = s_cam[11];

    // ---- hoist loop invariants into packed registers (feature pairs) ----
    u64 DIRF[F / 2], BASEF[F / 2], WD[F / 2], WC0[F / 2], WC1[F / 2], WC2[F / 2];
    #pragma unroll
    for (int jj = 0; jj < F / 2; jj++) {
        const int j0 = 2 * jj, j1 = 2 * jj + 1;
        float d0 = dx * s_Wf[0][j0] + dy * s_Wf[1][j0] + dz * s_Wf[2][j0];
        float d1 = dx * s_Wf[0][j1] + dy * s_Wf[1][j1] + dz * s_Wf[2][j1];
        float b0 = px * s_Wf[0][j0] + py * s_Wf[1][j0] + pz * s_Wf[2][j0] + s_bf[j0];
        float b1 = px * s_Wf[0][j1] + py * s_Wf[1][j1] + pz * s_Wf[2][j1] + s_bf[j1];
        DIRF[jj]  = pack2(d0, d1);
        BASEF[jj] = pack2(b0, b1);
        WD[jj]    = pack2(dn * s_WdFh[j0], dn * s_WdFh[j1]);   // dn folded
        WC0[jj]   = pack2(s_WcFh[j0][0], s_WcFh[j1][0]);
        WC1[jj]   = pack2(s_WcFh[j0][1], s_WcFh[j1][1]);
        WC2[jj]   = pack2(s_WcFh[j0][2], s_WcFh[j1][2]);
    }
    const float dird  = dx * s_Wd3[0] + dy * s_Wd3[1] + dz * s_Wd3[2];
    const float based = px * s_Wd3[0] + py * s_Wd3[1] + pz * s_Wd3[2] + s_bd;
    const u64 BASEDP = pack2(dn * based, 0.0f);               // density seed
    // dn also folds into the t-coefficient of density:
    const u64 DIRDP = pack2(dn * dird, 0.0f);

    const float nb0 = dx * s_negWc3[0][0] + dy * s_negWc3[1][0] + dz * s_negWc3[2][0] + s_negbc[0];
    const float nb1 = dx * s_negWc3[0][1] + dy * s_negWc3[1][1] + dz * s_negWc3[2][1] + s_negbc[1];
    const float nb2 = dx * s_negWc3[0][2] + dy * s_negWc3[1][2] + dz * s_negWc3[2][2] + s_negbc[2];
    const u64 NBP0 = pack2(nb0, 0.0f);
    const u64 NBP1 = pack2(nb1, 0.0f);
    const u64 NBP2 = pack2(nb2, 0.0f);

    // ---- local segment compositing (T starts at 1) ----
    float T = 1.0f;
    float c0 = 0.0f, c1 = 0.0f, c2 = 0.0f, depth = 0.0f;

    const u64* tt_base = reinterpret_cast<const u64*>(s_tt) + q;
    const float* dl_base = s_dl + q;

    #pragma unroll
    for (int i = 0; i < SPT; i++) {
        const u64 tt = tt_base[i * SEG];
        const float dl2 = dl_base[i * SEG];

        // feats: f2 = x + |x| = 2*relu(x), packed over feature pairs
        u64 F2[F / 2];
        #pragma unroll
        for (int jj = 0; jj < F / 2; jj++) {
            u64 x, ax;
            FMA2(x, tt, DIRF[jj], BASEF[jj]);
            ABS2(ax, x);
            ADD2(F2[jj], x, ax);
        }

        // density (scaled by dn): Dp = (t*dird*dn + based*dn, 0) + sum f2*WD
        u64 Dp;
        FMA2(Dp, tt, DIRDP, BASEDP);
        #pragma unroll
        for (int jj = 0; jj < F / 2; jj++)
            FMA2(Dp, F2[jj], WD[jj], Dp);
        float dlo, dhi;
        unpack2(Dp, dlo, dhi);
        float d = fmaxf(dlo + dhi, 0.0f);

        const float e  = ex2f(d * dl2);      // exp(-dens*delta*dn)
        const float Tn = T * e;
        const float wgt = T - Tn;
        T = Tn;

        // colors: packed partial sums, horizontal add, sigmoid
        u64 X0 = NBP0, X1 = NBP1, X2 = NBP2;
        #pragma unroll
        for (int jj = 0; jj < F / 2; jj++) {
            FMA2(X0, F2[jj], WC0[jj], X0);
            FMA2(X1, F2[jj], WC1[jj], X1);
            FMA2(X2, F2[jj], WC2[jj], X2);
        }
        float x0l, x0h, x1l, x1h, x2l, x2h;
        unpack2(X0, x0l, x0h);
        unpack2(X1, x1l, x1h);
        unpack2(X2, x2l, x2h);
        const float g0 = rcpf(1.0f + ex2f(x0l + x0h));
        const float g1 = rcpf(1.0f + ex2f(x1l + x1h));
        const float g2 = rcpf(1.0f + ex2f(x2l + x2h));

        c0 = fmaf(wgt, g0, c0);
        c1 = fmaf(wgt, g1, c1);
        c2 = fmaf(wgt, g2, c2);
        depth += wgt;
    }

    // ---- segmented combine across the 4 threads of this pixel ----
    const unsigned mask = 0xFFFFFFFFu;
    const float T0 = __shfl_sync(mask, T, 0, 4);
    const float T1 = __shfl_sync(mask, T, 1, 4);
    const float T2 = __shfl_sync(mask, T, 2, 4);
    float p = 1.0f;
    if (q > 0) p *= T0;
    if (q > 1) p *= T1;
    if (q > 2) p *= T2;
    c0 *= p; c1 *= p; c2 *= p; depth *= p;

    #pragma unroll
    for (int off = 1; off < SEG; off <<= 1) {
        c0    += __shfl_xor_sync(mask, c0, off, 4);
        c1    += __shfl_xor_sync(mask, c1, off, 4);
        c2    += __shfl_xor_sync(mask, c2, off, 4);
        depth += __shfl_xor_sync(mask, depth, off, 4);
    }

    if (q == 0) {
        out[pix * 3 + 0] = c0;
        out[pix * 3 + 1] = c1;
        out[pix * 3 + 2] = c2;
        out[NPIX * 3 + pix] = depth;
    }
}

extern "C" void kernel_launch(void* const* d_in, const int* in_sizes, int n_in,
                              void* d_out, int out_size)
{
    const float* positions = (const float*)d_in[0];
    const float* forwards  = (const float*)d_in[1];
    const float* ups       = (const float*)d_in[2];
    const float* normal    = (const float*)d_in[3];
    const float* Wf        = (const float*)d_in[4];
    const float* bf        = (const float*)d_in[5];
    const float* Wd        = (const float*)d_in[6];
    const float* bd        = (const float*)d_in[7];
    const float* Wc        = (const float*)d_in[8];
    const float* bc        = (const float*)d_in[9];
    float* out = (float*)d_out;

    const int threads = 128;
    const int blocks = (NPIX * SEG) / threads;   // 1250
    render_kernel<<<blocks, threads>>>(positions, forwards, ups, normal,
                                       Wf, bf, Wd, bd, Wc, bc, out);
}